// round 12
// baseline (speedup 1.0000x reference)
#include <cuda_runtime.h>
#include <math.h>

#define BB 8
#define TT 256
#define DD 12
#define HH 4
#define HD 3
#define NTOK (BB*TT)
#define KVS 260   // kT/vT row stride: 260*4B = 16B-aligned, 260 % 32 = 4 (bank-skewed)

// ---------------------------------------------------------------------------
// ONE fused kernel: QKV projection (block-local recompute of full-batch K/V)
// + attention + output projection + analytic quantum expectation values.
// Block = 8 consecutive tokens of one batch, 256 threads (8 warps).
//   Warp (wid) = head h = wid&3, token-quad tg = (wid>>2)*4.
//   out[k] = prod_{j=0..k} cos(phi_j) (k>=1) ; out[0] = prod_{j=1..11} cos(phi_j)
//   phi = ctx @ wo.T + bo + theta  (quantum circuit collapsed analytically)
// ---------------------------------------------------------------------------
__global__ __launch_bounds__(256)
void fused_attn_quantum_kernel(const float* __restrict__ x,
                               const float* __restrict__ wq,
                               const float* __restrict__ wk,
                               const float* __restrict__ wv,
                               const float* __restrict__ bq,
                               const float* __restrict__ bk,
                               const float* __restrict__ bv,
                               const float* __restrict__ wo,
                               const float* __restrict__ bo,
                               const float* __restrict__ theta,
                               float* __restrict__ out)
{
    const int tid   = threadIdx.x;
    const int wid   = tid >> 5;
    const int lane  = tid & 31;
    const int h     = wid & 3;          // head for attention phase
    const int tg    = (wid >> 2) * 4;   // token-quad base (0 or 4)
    const int n0    = blockIdx.x * 8;   // 8 tokens, same batch (8 | 256)
    const int b     = n0 >> 8;
    const int tloc0 = n0 & 255;         // block's first token within batch

    __shared__ float xs[TT][DD + 1];          // x[b], padded
    __shared__ float kTs[DD * KVS];           // [h*3+i][t], t contiguous
    __shared__ float vTs[DD * KVS];
    __shared__ float wqs[DD * DD], wks[DD * DD], wvs[DD * DD], wos[DD * DD];
    __shared__ float bqs[DD], bks[DD], bvs[DD], bts[DD];
    __shared__ float qs[8][DD + 1];           // block's 8 q rows (pre-scaled)
    __shared__ float ctxs[8][DD + 1];

    // ---- phase 1: stage x[b] + weights + biases (coalesced) ----
    const float* xb = x + b * TT * DD;
    #pragma unroll
    for (int i = 0; i < DD; i++) {
        const int idx = tid + 256 * i;        // 0..3071
        const int r = idx / DD, c = idx - r * DD;
        xs[r][c] = xb[idx];
    }
    if (tid < DD * DD) {                      // 144 < 256
        wqs[tid] = wq[tid]; wks[tid] = wk[tid];
        wvs[tid] = wv[tid]; wos[tid] = wo[tid];
    }
    if (tid < DD) {
        bqs[tid] = bq[tid]; bks[tid] = bk[tid]; bvs[tid] = bv[tid];
        bts[tid] = bo[tid] + theta[tid];
    }
    __syncthreads();

    // ---- phase 2: full-batch K/V projection into smem (block-local) ----
    #pragma unroll
    for (int i = 0; i < DD; i++) {
        const int p = tid + 256 * i;          // 0..3071
        const int t = p / DD, d = p - t * DD; // d = h*3 + subdim directly
        float ak = bks[d], av = bvs[d];
        #pragma unroll
        for (int j = 0; j < DD; j++) {
            const float xj = xs[t][j];
            ak = fmaf(xj, wks[d * DD + j], ak);
            av = fmaf(xj, wvs[d * DD + j], av);
        }
        kTs[d * KVS + t] = ak;
        vTs[d * KVS + t] = av;
    }
    // q for this block's 8 tokens (96 outputs), pre-scaled by 1/sqrt(hd)
    if (tid < 8 * DD) {
        const int t = tid / DD, d = tid - t * DD;
        float aq = bqs[d];
        #pragma unroll
        for (int j = 0; j < DD; j++)
            aq = fmaf(xs[tloc0 + t][j], wqs[d * DD + j], aq);
        qs[t][d] = aq * 0.57735026919f;
    }
    __syncthreads();

    // ---- phase 3: attention. Warp = (head h, token-quad tg). ----
    // K/V from smem: 8 keys/lane via LDS.128, loaded once for 4 queries.
    const float4* kx = (const float4*)(kTs + (h * HD + 0) * KVS);
    const float4* ky = (const float4*)(kTs + (h * HD + 1) * KVS);
    const float4* kz = (const float4*)(kTs + (h * HD + 2) * KVS);
    const float4* vx = (const float4*)(vTs + (h * HD + 0) * KVS);
    const float4* vy = (const float4*)(vTs + (h * HD + 1) * KVS);
    const float4* vz = (const float4*)(vTs + (h * HD + 2) * KVS);
    const float4 kxa = kx[lane], kxb = kx[32 + lane];
    const float4 kya = ky[lane], kyb = ky[32 + lane];
    const float4 kza = kz[lane], kzb = kz[32 + lane];
    const float4 vxa = vx[lane], vxb = vx[32 + lane];
    const float4 vya = vy[lane], vyb = vy[32 + lane];
    const float4 vza = vz[lane], vzb = vz[32 + lane];

    #pragma unroll
    for (int t = 0; t < 4; t++) {
        const float q0 = qs[tg + t][h * HD + 0];   // smem broadcast
        const float q1 = qs[tg + t][h * HD + 1];
        const float q2 = qs[tg + t][h * HD + 2];

        float l = 0.f, a0 = 0.f, a1 = 0.f, a2 = 0.f;
        {   // no-max softmax (scores O(10), fp32-safe), inline exp->accumulate
            float p;
            p = __expf(q0*kxa.x + q1*kya.x + q2*kza.x);
            l += p; a0 = fmaf(p, vxa.x, a0); a1 = fmaf(p, vya.x, a1); a2 = fmaf(p, vza.x, a2);
            p = __expf(q0*kxa.y + q1*kya.y + q2*kza.y);
            l += p; a0 = fmaf(p, vxa.y, a0); a1 = fmaf(p, vya.y, a1); a2 = fmaf(p, vza.y, a2);
            p = __expf(q0*kxa.z + q1*kya.z + q2*kza.z);
            l += p; a0 = fmaf(p, vxa.z, a0); a1 = fmaf(p, vya.z, a1); a2 = fmaf(p, vza.z, a2);
            p = __expf(q0*kxa.w + q1*kya.w + q2*kza.w);
            l += p; a0 = fmaf(p, vxa.w, a0); a1 = fmaf(p, vya.w, a1); a2 = fmaf(p, vza.w, a2);
            p = __expf(q0*kxb.x + q1*kyb.x + q2*kzb.x);
            l += p; a0 = fmaf(p, vxb.x, a0); a1 = fmaf(p, vyb.x, a1); a2 = fmaf(p, vzb.x, a2);
            p = __expf(q0*kxb.y + q1*kyb.y + q2*kzb.y);
            l += p; a0 = fmaf(p, vxb.y, a0); a1 = fmaf(p, vyb.y, a1); a2 = fmaf(p, vzb.y, a2);
            p = __expf(q0*kxb.z + q1*kyb.z + q2*kzb.z);
            l += p; a0 = fmaf(p, vxb.z, a0); a1 = fmaf(p, vyb.z, a1); a2 = fmaf(p, vzb.z, a2);
            p = __expf(q0*kxb.w + q1*kyb.w + q2*kzb.w);
            l += p; a0 = fmaf(p, vxb.w, a0); a1 = fmaf(p, vyb.w, a1); a2 = fmaf(p, vzb.w, a2);
        }

        // split reduction: 2 butterfly levels on all 4, select by lane group,
        // 3 butterfly levels on one value.
        #pragma unroll
        for (int off = 16; off >= 8; off >>= 1) {
            l  += __shfl_xor_sync(0xFFFFFFFFu, l,  off);
            a0 += __shfl_xor_sync(0xFFFFFFFFu, a0, off);
            a1 += __shfl_xor_sync(0xFFFFFFFFu, a1, off);
            a2 += __shfl_xor_sync(0xFFFFFFFFu, a2, off);
        }
        float v = (lane < 8) ? l : (lane < 16) ? a0 : (lane < 24) ? a1 : a2;
        #pragma unroll
        for (int off = 4; off >= 1; off >>= 1)
            v += __shfl_xor_sync(0xFFFFFFFFu, v, off);
        const float ltot = __shfl_sync(0xFFFFFFFFu, v, 0);
        if ((lane & 7) == 0 && lane != 0)
            ctxs[tg + t][h * HD + (lane >> 3) - 1] = __fdividef(v, ltot);
    }
    __syncthreads();

    // ---- phase 4: tail, warp w -> token w (lanes 0..11 active math) ----
    {
        const int t = wid;               // 8 warps -> 8 tokens
        const int w = lane;
        float c = 1.0f;
        if (w < DD) {
            float a = bts[w];
            #pragma unroll
            for (int j = 0; j < DD; j++) a = fmaf(ctxs[t][j], wos[w * DD + j], a);
            c = __cosf(a);
        }
        // inclusive product scan: d_0 = 1, d_w = c_w (1<=w<12) -> S_w = c_1..c_w
        float d = (w >= 1 && w < DD) ? c : 1.0f;
        #pragma unroll
        for (int off = 1; off <= 8; off <<= 1) {
            const float s = __shfl_up_sync(0xFFFFFFFFu, d, off);
            if (lane >= off) d *= s;
        }
        const float c0  = __shfl_sync(0xFFFFFFFFu, c, 0);
        const float s11 = __shfl_sync(0xFFFFFFFFu, d, 11);
        if (w < DD)
            out[(n0 + t) * DD + w] = (w == 0) ? s11 : c0 * d;
    }
}

extern "C" void kernel_launch(void* const* d_in, const int* in_sizes, int n_in,
                              void* d_out, int out_size)
{
    const float* x     = (const float*)d_in[0];
    const float* wq    = (const float*)d_in[1];
    const float* wk    = (const float*)d_in[2];
    const float* wv    = (const float*)d_in[3];
    const float* bq    = (const float*)d_in[4];
    const float* bk    = (const float*)d_in[5];
    const float* bv    = (const float*)d_in[6];
    const float* wo    = (const float*)d_in[7];
    const float* bo    = (const float*)d_in[8];
    const float* theta = (const float*)d_in[9];
    float* out = (float*)d_out;

    fused_attn_quantum_kernel<<<NTOK / 8, 256>>>(x, wq, wk, wv, bq, bk, bv,
                                                 wo, bo, theta, out);
}

// round 13
// speedup vs baseline: 1.5861x; 1.5861x over previous
#include <cuda_runtime.h>
#include <math.h>

#define BB 8
#define TT 256
#define DD 12
#define HH 4
#define HD 3
#define NTOK (BB*TT)

// scratch (no cudaMalloc allowed)
__device__ float g_kT[BB * HH * HD * TT]; // [b][h][i][t] key-major rows (float4-aligned)
__device__ float g_vT[BB * HH * HD * TT];

// ---------------------------------------------------------------------------
// K1: K/V projection only (Q moved into consumer's PDL overlap window).
// 16 tokens/block x 12 dims = 192 threads. Signals dependents immediately.
// ---------------------------------------------------------------------------
__global__ __launch_bounds__(192)
void kv_kernel(const float* __restrict__ x,
               const float* __restrict__ wk, const float* __restrict__ wv,
               const float* __restrict__ bk, const float* __restrict__ bv)
{
    asm volatile("griddepcontrol.launch_dependents;");

    const int tid = threadIdx.x;
    const int n0  = blockIdx.x * 16;

    __shared__ float xs[16][DD + 1];
    __shared__ float wks[DD * DD], wvs[DD * DD];
    __shared__ float bs[2 * DD];

    if (tid < DD * DD) { wks[tid] = wk[tid]; wvs[tid] = wv[tid]; }
    if (tid < DD) { bs[tid] = bk[tid]; bs[DD + tid] = bv[tid]; }
    {   // coalesced: 192 floats = 16 rows x 12
        const int r = tid / DD, c = tid - r * DD;
        xs[r][c] = x[n0 * DD + tid];
    }
    __syncthreads();

    const int t = tid / DD;
    const int d = tid - t * DD;
    const int n = n0 + t;

    float ak = bs[d], av = bs[DD + d];
    #pragma unroll
    for (int j = 0; j < DD; j++) {
        const float xj = xs[t][j];
        ak = fmaf(xj, wks[d * DD + j], ak);
        av = fmaf(xj, wvs[d * DD + j], av);
    }

    const int b = n >> 8, tt = n & 255;
    const int h = d / HD, i = d - h * HD;
    const int base = ((b * HH + h) * HD + i) * TT + tt;
    g_kT[base] = ak;
    g_vT[base] = av;
}

// ---------------------------------------------------------------------------
// K2: fused Q-projection + attention + output projection + quantum expvals.
// Block = 8 consecutive tokens, 8 warps (256 thr). Warp = (head h = wid&3,
// token-quad tg = (wid>>2)*4), 4 tokens/warp (measured-optimal shape).
// PDL: x/wq/bq/wo/bo/theta staging AND the whole Q projection run BEFORE
// griddepcontrol.wait — hidden under the producer kernel. No-max softmax
// (scores O(10), fp32-safe), inline exp->accumulate, split shfl reduction.
//   out[k] = prod_{j=0..k} cos(phi_j) (k>=1) ; out[0] = prod_{j=1..11}
//   phi = ctx @ wo.T + bo + theta   (quantum circuit collapsed analytically)
// ---------------------------------------------------------------------------
__global__ __launch_bounds__(256)
void attn_quantum_kernel(const float* __restrict__ x,
                         const float* __restrict__ wq,
                         const float* __restrict__ bq,
                         const float* __restrict__ wo,
                         const float* __restrict__ bo,
                         const float* __restrict__ theta,
                         float* __restrict__ out)
{
    const int tid  = threadIdx.x;
    const int wid  = tid >> 5;
    const int h    = wid & 3;           // head
    const int tg   = (wid >> 2) * 4;    // token-quad base within block (0 or 4)
    const int lane = tid & 31;
    const int n0   = blockIdx.x * 8;    // 8 tokens, same batch (8 | 256)
    const int b    = n0 >> 8;

    __shared__ float xs[8][DD + 1];           // this block's 8 x rows
    __shared__ float wqs[DD * DD], wos[DD * DD];
    __shared__ float bqs[DD], bts[DD];
    __shared__ float ctxs[8][DD + 1];

    // ---- pre-wait preamble: stage independent inputs (overlaps producer) ----
    if (tid < 8 * DD) {                       // 96 floats, coalesced
        const int r = tid / DD, c = tid - r * DD;
        xs[r][c] = x[n0 * DD + tid];
    }
    if (tid < DD * DD) { wqs[tid] = wq[tid]; wos[tid] = wo[tid]; }
    if (tid < DD) { bqs[tid] = bq[tid]; bts[tid] = bo[tid] + theta[tid]; }
    __syncthreads();

    // ---- pre-wait Q projection, warp-local (still overlapped) ----
    // lane e < 12: token tg + e/3, head-dim i = e%3  ->  qv (pre-scaled)
    float qv;
    {
        const int e  = (lane < 12) ? lane : 0;
        const int tq = e / 3;
        const int d  = h * HD + (e - tq * 3);
        float a = bqs[d];
        #pragma unroll
        for (int j = 0; j < DD; j++) a = fmaf(xs[tg + tq][j], wqs[d * DD + j], a);
        qv = a * 0.57735026919f;
    }

    asm volatile("griddepcontrol.wait;");

    // ---- K/V for head h: 8 keys per lane, loaded ONCE for 4 queries ----
    const float4* kb4 = (const float4*)(g_kT + (b * HH + h) * HD * TT);
    const float4* vb4 = (const float4*)(g_vT + (b * HH + h) * HD * TT);
    const float4 kxa = kb4[lane],       kxb = kb4[32 + lane];
    const float4 kya = kb4[64 + lane],  kyb = kb4[96 + lane];
    const float4 kza = kb4[128 + lane], kzb = kb4[160 + lane];
    const float4 vxa = vb4[lane],       vxb = vb4[32 + lane];
    const float4 vya = vb4[64 + lane],  vyb = vb4[96 + lane];
    const float4 vza = vb4[128 + lane], vzb = vb4[160 + lane];

    #pragma unroll
    for (int t = 0; t < 4; t++) {
        const float q0 = __shfl_sync(0xFFFFFFFFu, qv, t * 3 + 0);
        const float q1 = __shfl_sync(0xFFFFFFFFu, qv, t * 3 + 1);
        const float q2 = __shfl_sync(0xFFFFFFFFu, qv, t * 3 + 2);

        float l = 0.f, a0 = 0.f, a1 = 0.f, a2 = 0.f;
        {   // inline exp -> accumulate
            float p;
            p = __expf(q0*kxa.x + q1*kya.x + q2*kza.x);
            l += p; a0 = fmaf(p, vxa.x, a0); a1 = fmaf(p, vya.x, a1); a2 = fmaf(p, vza.x, a2);
            p = __expf(q0*kxa.y + q1*kya.y + q2*kza.y);
            l += p; a0 = fmaf(p, vxa.y, a0); a1 = fmaf(p, vya.y, a1); a2 = fmaf(p, vza.y, a2);
            p = __expf(q0*kxa.z + q1*kya.z + q2*kza.z);
            l += p; a0 = fmaf(p, vxa.z, a0); a1 = fmaf(p, vya.z, a1); a2 = fmaf(p, vza.z, a2);
            p = __expf(q0*kxa.w + q1*kya.w + q2*kza.w);
            l += p; a0 = fmaf(p, vxa.w, a0); a1 = fmaf(p, vya.w, a1); a2 = fmaf(p, vza.w, a2);
            p = __expf(q0*kxb.x + q1*kyb.x + q2*kzb.x);
            l += p; a0 = fmaf(p, vxb.x, a0); a1 = fmaf(p, vyb.x, a1); a2 = fmaf(p, vzb.x, a2);
            p = __expf(q0*kxb.y + q1*kyb.y + q2*kzb.y);
            l += p; a0 = fmaf(p, vxb.y, a0); a1 = fmaf(p, vyb.y, a1); a2 = fmaf(p, vzb.y, a2);
            p = __expf(q0*kxb.z + q1*kyb.z + q2*kzb.z);
            l += p; a0 = fmaf(p, vxb.z, a0); a1 = fmaf(p, vyb.z, a1); a2 = fmaf(p, vzb.z, a2);
            p = __expf(q0*kxb.w + q1*kyb.w + q2*kzb.w);
            l += p; a0 = fmaf(p, vxb.w, a0); a1 = fmaf(p, vyb.w, a1); a2 = fmaf(p, vzb.w, a2);
        }

        // split reduction: 2 butterfly levels on all 4, select by lane group,
        // 3 butterfly levels on one value.
        #pragma unroll
        for (int off = 16; off >= 8; off >>= 1) {
            l  += __shfl_xor_sync(0xFFFFFFFFu, l,  off);
            a0 += __shfl_xor_sync(0xFFFFFFFFu, a0, off);
            a1 += __shfl_xor_sync(0xFFFFFFFFu, a1, off);
            a2 += __shfl_xor_sync(0xFFFFFFFFu, a2, off);
        }
        float v = (lane < 8) ? l : (lane < 16) ? a0 : (lane < 24) ? a1 : a2;
        #pragma unroll
        for (int off = 4; off >= 1; off >>= 1)
            v += __shfl_xor_sync(0xFFFFFFFFu, v, off);
        // lanes 0-7: total l ; 8-15: a0 ; 16-23: a1 ; 24-31: a2
        const float ltot = __shfl_sync(0xFFFFFFFFu, v, 0);
        if ((lane & 7) == 0 && lane != 0)
            ctxs[tg + t][h * HD + (lane >> 3) - 1] = __fdividef(v, ltot);
    }
    __syncthreads();

    // ---- tail: warp w handles token w (lanes 0..11 active math) ----
    {
        const int t = wid;               // 8 warps -> 8 tokens
        const int w = lane;
        float c = 1.0f;
        if (w < DD) {
            float a = bts[w];
            #pragma unroll
            for (int j = 0; j < DD; j++) a = fmaf(ctxs[t][j], wos[w * DD + j], a);
            c = __cosf(a);
        }
        // inclusive product scan: d_0 = 1, d_w = c_w (1<=w<12) -> S_w = c_1..c_w
        float d = (w >= 1 && w < DD) ? c : 1.0f;
        #pragma unroll
        for (int off = 1; off <= 8; off <<= 1) {
            const float s = __shfl_up_sync(0xFFFFFFFFu, d, off);
            if (lane >= off) d *= s;
        }
        const float c0  = __shfl_sync(0xFFFFFFFFu, c, 0);
        const float s11 = __shfl_sync(0xFFFFFFFFu, d, 11);
        if (w < DD)
            out[(n0 + t) * DD + w] = (w == 0) ? s11 : c0 * d;
    }
}

extern "C" void kernel_launch(void* const* d_in, const int* in_sizes, int n_in,
                              void* d_out, int out_size)
{
    const float* x     = (const float*)d_in[0];
    const float* wq    = (const float*)d_in[1];
    const float* wk    = (const float*)d_in[2];
    const float* wv    = (const float*)d_in[3];
    const float* bq    = (const float*)d_in[4];
    const float* bk    = (const float*)d_in[5];
    const float* bv    = (const float*)d_in[6];
    const float* wo    = (const float*)d_in[7];
    const float* bo    = (const float*)d_in[8];
    const float* theta = (const float*)d_in[9];
    float* out = (float*)d_out;

    kv_kernel<<<NTOK / 16, 192>>>(x, wk, wv, bk, bv);

    // PDL launch: overlap this grid's ramp + preamble + Q projection with kv
    cudaLaunchConfig_t cfg = {};
    cfg.gridDim  = dim3(NTOK / 8, 1, 1);
    cfg.blockDim = dim3(256, 1, 1);
    cfg.dynamicSmemBytes = 0;
    cfg.stream = 0;   // same (capture) stream as the <<<>>> launch above
    cudaLaunchAttribute attr[1];
    attr[0].id = cudaLaunchAttributeProgrammaticStreamSerialization;
    attr[0].val.programmaticStreamSerializationAllowed = 1;
    cfg.attrs = attr;
    cfg.numAttrs = 1;
    cudaLaunchKernelEx(&cfg, attn_quantum_kernel, x, wq, bq, wo, bo, theta, out);
}

// round 15
// speedup vs baseline: 1.6278x; 1.0263x over previous
#include <cuda_runtime.h>
#include <math.h>

#define BB 8
#define TT 256
#define DD 12
#define HH 4
#define HD 3
#define NTOK (BB*TT)

// scratch (no cudaMalloc allowed)
__device__ float g_kT[BB * HH * HD * TT]; // [b][h][i][t] key-major rows (float4-aligned)
__device__ float g_vT[BB * HH * HD * TT];

// ---------------------------------------------------------------------------
// K1: K/V projection only (Q lives in the consumer's PDL overlap window).
// 16 tokens/block x 12 dims = 192 threads. Signals dependents immediately.
// ---------------------------------------------------------------------------
__global__ __launch_bounds__(192)
void kv_kernel(const float* __restrict__ x,
               const float* __restrict__ wk, const float* __restrict__ wv,
               const float* __restrict__ bk, const float* __restrict__ bv)
{
    asm volatile("griddepcontrol.launch_dependents;");

    const int tid = threadIdx.x;
    const int n0  = blockIdx.x * 16;

    __shared__ float xs[16][DD + 1];
    __shared__ float wks[DD * DD], wvs[DD * DD];
    __shared__ float bs[2 * DD];

    if (tid < DD * DD) { wks[tid] = wk[tid]; wvs[tid] = wv[tid]; }
    if (tid < DD) { bs[tid] = bk[tid]; bs[DD + tid] = bv[tid]; }
    {   // coalesced: 192 floats = 16 rows x 12
        const int r = tid / DD, c = tid - r * DD;
        xs[r][c] = x[n0 * DD + tid];
    }
    __syncthreads();

    const int t = tid / DD;
    const int d = tid - t * DD;
    const int n = n0 + t;

    float ak = bs[d], av = bs[DD + d];
    #pragma unroll
    for (int j = 0; j < DD; j++) {
        const float xj = xs[t][j];
        ak = fmaf(xj, wks[d * DD + j], ak);
        av = fmaf(xj, wvs[d * DD + j], av);
    }

    const int b = n >> 8, tt = n & 255;
    const int h = d / HD, i = d - h * HD;
    const int base = ((b * HH + h) * HD + i) * TT + tt;
    g_kT[base] = ak;
    g_vT[base] = av;
}

// ---------------------------------------------------------------------------
// K2: fused Q-projection + attention + output projection + quantum expvals.
// Geometry: 512 blocks x 128 thr — the measured-fastest post-wait shape.
// Block = 4 consecutive tokens; warp h = head h handles ALL 4 tokens (K/V in
// registers, 4x reuse). PDL: input staging + the whole Q projection run
// BEFORE griddepcontrol.wait (hidden under the producer). No-max softmax
// (scores O(10), fp32-safe), inline exp->accumulate, split shfl reduction.
//   out[k] = prod_{j=0..k} cos(phi_j) (k>=1) ; out[0] = prod_{j=1..11}
//   phi = ctx @ wo.T + bo + theta   (quantum circuit collapsed analytically)
// ---------------------------------------------------------------------------
__global__ __launch_bounds__(128)
void attn_quantum_kernel(const float* __restrict__ x,
                         const float* __restrict__ wq,
                         const float* __restrict__ bq,
                         const float* __restrict__ wo,
                         const float* __restrict__ bo,
                         const float* __restrict__ theta,
                         float* __restrict__ out)
{
    const int tid  = threadIdx.x;
    const int h    = tid >> 5;          // warp = head
    const int lane = tid & 31;
    const int n0   = blockIdx.x * 4;    // 4 tokens, same batch (4 | 256)
    const int b    = n0 >> 8;

    __shared__ float xs[4][DD + 1];           // this block's 4 x rows
    __shared__ float wqs[DD * DD], wos[DD * DD];
    __shared__ float bqs[DD], bts[DD];
    __shared__ float ctxs[4][DD + 1];

    // ---- pre-wait preamble: stage independent inputs (overlaps producer) ----
    if (tid < 4 * DD) {                       // 48 floats, coalesced
        const int r = tid / DD, c = tid - r * DD;
        xs[r][c] = x[n0 * DD + tid];
    }
    if (tid < DD * DD - 128) { wqs[128 + tid] = wq[128 + tid]; wos[128 + tid] = wo[128 + tid]; }
    wqs[tid] = wq[tid]; wos[tid] = wo[tid];
    if (tid < DD) { bqs[tid] = bq[tid]; bts[tid] = bo[tid] + theta[tid]; }
    __syncthreads();

    // ---- pre-wait Q projection, warp-local (still overlapped) ----
    // lane e < 12: token e/3, head-dim i = e%3  ->  qv (pre-scaled)
    float qv;
    {
        const int e  = (lane < 12) ? lane : 0;
        const int tq = e / 3;
        const int d  = h * HD + (e - tq * 3);
        float a = bqs[d];
        #pragma unroll
        for (int j = 0; j < DD; j++) a = fmaf(xs[tq][j], wqs[d * DD + j], a);
        qv = a * 0.57735026919f;
    }

    asm volatile("griddepcontrol.wait;");

    // ---- K/V for head h: 8 keys per lane, loaded ONCE for 4 queries ----
    const float4* kb4 = (const float4*)(g_kT + (b * HH + h) * HD * TT);
    const float4* vb4 = (const float4*)(g_vT + (b * HH + h) * HD * TT);
    const float4 kxa = kb4[lane],       kxb = kb4[32 + lane];
    const float4 kya = kb4[64 + lane],  kyb = kb4[96 + lane];
    const float4 kza = kb4[128 + lane], kzb = kb4[160 + lane];
    const float4 vxa = vb4[lane],       vxb = vb4[32 + lane];
    const float4 vya = vb4[64 + lane],  vyb = vb4[96 + lane];
    const float4 vza = vb4[128 + lane], vzb = vb4[160 + lane];

    #pragma unroll
    for (int t = 0; t < 4; t++) {
        const float q0 = __shfl_sync(0xFFFFFFFFu, qv, t * 3 + 0);
        const float q1 = __shfl_sync(0xFFFFFFFFu, qv, t * 3 + 1);
        const float q2 = __shfl_sync(0xFFFFFFFFu, qv, t * 3 + 2);

        float l = 0.f, a0 = 0.f, a1 = 0.f, a2 = 0.f;
        {   // inline exp -> accumulate
            float p;
            p = __expf(q0*kxa.x + q1*kya.x + q2*kza.x);
            l += p; a0 = fmaf(p, vxa.x, a0); a1 = fmaf(p, vya.x, a1); a2 = fmaf(p, vza.x, a2);
            p = __expf(q0*kxa.y + q1*kya.y + q2*kza.y);
            l += p; a0 = fmaf(p, vxa.y, a0); a1 = fmaf(p, vya.y, a1); a2 = fmaf(p, vza.y, a2);
            p = __expf(q0*kxa.z + q1*kya.z + q2*kza.z);
            l += p; a0 = fmaf(p, vxa.z, a0); a1 = fmaf(p, vya.z, a1); a2 = fmaf(p, vza.z, a2);
            p = __expf(q0*kxa.w + q1*kya.w + q2*kza.w);
            l += p; a0 = fmaf(p, vxa.w, a0); a1 = fmaf(p, vya.w, a1); a2 = fmaf(p, vza.w, a2);
            p = __expf(q0*kxb.x + q1*kyb.x + q2*kzb.x);
            l += p; a0 = fmaf(p, vxb.x, a0); a1 = fmaf(p, vyb.x, a1); a2 = fmaf(p, vzb.x, a2);
            p = __expf(q0*kxb.y + q1*kyb.y + q2*kzb.y);
            l += p; a0 = fmaf(p, vxb.y, a0); a1 = fmaf(p, vyb.y, a1); a2 = fmaf(p, vzb.y, a2);
            p = __expf(q0*kxb.z + q1*kyb.z + q2*kzb.z);
            l += p; a0 = fmaf(p, vxb.z, a0); a1 = fmaf(p, vyb.z, a1); a2 = fmaf(p, vzb.z, a2);
            p = __expf(q0*kxb.w + q1*kyb.w + q2*kzb.w);
            l += p; a0 = fmaf(p, vxb.w, a0); a1 = fmaf(p, vyb.w, a1); a2 = fmaf(p, vzb.w, a2);
        }

        // split reduction: 2 butterfly levels on all 4, select by lane group,
        // 3 butterfly levels on one value.
        #pragma unroll
        for (int off = 16; off >= 8; off >>= 1) {
            l  += __shfl_xor_sync(0xFFFFFFFFu, l,  off);
            a0 += __shfl_xor_sync(0xFFFFFFFFu, a0, off);
            a1 += __shfl_xor_sync(0xFFFFFFFFu, a1, off);
            a2 += __shfl_xor_sync(0xFFFFFFFFu, a2, off);
        }
        float v = (lane < 8) ? l : (lane < 16) ? a0 : (lane < 24) ? a1 : a2;
        #pragma unroll
        for (int off = 4; off >= 1; off >>= 1)
            v += __shfl_xor_sync(0xFFFFFFFFu, v, off);
        // lanes 0-7: total l ; 8-15: a0 ; 16-23: a1 ; 24-31: a2
        const float ltot = __shfl_sync(0xFFFFFFFFu, v, 0);
        if ((lane & 7) == 0 && lane != 0)
            ctxs[t][h * HD + (lane >> 3) - 1] = __fdividef(v, ltot);
    }
    __syncthreads();

    // ---- tail: warp t handles token t (lanes 0..11 active math) ----
    {
        const int t = h;                 // 4 warps -> 4 tokens
        const int w = lane;
        float c = 1.0f;
        if (w < DD) {
            float a = bts[w];
            #pragma unroll
            for (int j = 0; j < DD; j++) a = fmaf(ctxs[t][j], wos[w * DD + j], a);
            c = __cosf(a);
        }
        // inclusive product scan: d_0 = 1, d_w = c_w (1<=w<12) -> S_w = c_1..c_w
        float d = (w >= 1 && w < DD) ? c : 1.0f;
        #pragma unroll
        for (int off = 1; off <= 8; off <<= 1) {
            const float s = __shfl_up_sync(0xFFFFFFFFu, d, off);
            if (lane >= off) d *= s;
        }
        const float c0  = __shfl_sync(0xFFFFFFFFu, c, 0);
        const float s11 = __shfl_sync(0xFFFFFFFFu, d, 11);
        if (w < DD)
            out[(n0 + t) * DD + w] = (w == 0) ? s11 : c0 * d;
    }
}

extern "C" void kernel_launch(void* const* d_in, const int* in_sizes, int n_in,
                              void* d_out, int out_size)
{
    const float* x     = (const float*)d_in[0];
    const float* wq    = (const float*)d_in[1];
    const float* wk    = (const float*)d_in[2];
    const float* wv    = (const float*)d_in[3];
    const float* bq    = (const float*)d_in[4];
    const float* bk    = (const float*)d_in[5];
    const float* bv    = (const float*)d_in[6];
    const float* wo    = (const float*)d_in[7];
    const float* bo    = (const float*)d_in[8];
    const float* theta = (const float*)d_in[9];
    float* out = (float*)d_out;

    kv_kernel<<<NTOK / 16, 192>>>(x, wk, wv, bk, bv);

    // PDL launch: overlap this grid's ramp + preamble + Q projection with kv
    cudaLaunchConfig_t cfg = {};
    cfg.gridDim  = dim3(NTOK / 4, 1, 1);
    cfg.blockDim = dim3(128, 1, 1);
    cfg.dynamicSmemBytes = 0;
    cfg.stream = 0;   // same (capture) stream as the <<<>>> launch above
    cudaLaunchAttribute attr[1];
    attr[0].id = cudaLaunchAttributeProgrammaticStreamSerialization;
    attr[0].val.programmaticStreamSerializationAllowed = 1;
    cfg.attrs = attr;
    cfg.numAttrs = 1;
    cudaLaunchKernelEx(&cfg, attn_quantum_kernel, x, wq, bq, wo, bo, theta, out);
}